// round 2
// baseline (speedup 1.0000x reference)
#include <cuda_runtime.h>
#include <cuda_bf16.h>

// Problem constants
#define BATCH 2
#define CCH   256
#define HH    192
#define WW    192
#define HW    (HH * WW)          // 36864
#define CHW   (CCH * HW)

// Scratch (allocation-free rule: __device__ globals)
__device__ float g_tmp [BATCH * CCH * HH * WW];  // NCHW: conv_1x5 output
__device__ float g_feat[BATCH * HH * WW * CCH];  // NHWC: conv_5x1 + conv_1x1 output

// -------- GEMM tiling --------
#define BM 128
#define BN 64
#define BK 16
#define TM 8
#define TN 4

// ============================================================
// Kernel 1: tmp = conv_1x5(x) + b15      (implicit GEMM, K = C*5 = 1280)
// A = w15 flat [256][1280], B = im2col of x (shifts along w), out NCHW.
// ============================================================
__global__ __launch_bounds__(256) void conv15_kernel(
    const float* __restrict__ x,
    const float* __restrict__ w15,
    const float* __restrict__ b15)
{
    const int nb = blockIdx.x;            // 0 .. BATCH*HH*3 - 1
    const int b  = nb / (HH * 3);
    const int r  = nb % (HH * 3);
    const int h  = r / 3;
    const int w0 = (r % 3) * BN;
    const int co0 = blockIdx.y * BM;

    __shared__ float As[BK][BM];
    __shared__ float Bs[BK][BN];

    const int tid = threadIdx.x;
    const int tx = tid % 16;              // n group
    const int ty = tid / 16;              // m group
    float acc[TM][TN] = {};

    // A loader: each thread reads 8 consecutive k of one m-row (one full 32B sector)
    const int am  = tid % BM;             // 0..127
    const int ak0 = (tid / BM) * 8;       // 0 or 8
    const float* __restrict__ Arow = w15 + (size_t)(co0 + am) * (CCH * 5);

    // B loader: 1024 elems / 256 threads = 4 consecutive floats
    const int bk  = tid / 16;             // 0..15
    const int bn0 = (tid % 16) * 4;

    const float* __restrict__ xrow = x + (size_t)b * CHW + (size_t)h * WW;

    for (int k0 = 0; k0 < CCH * 5; k0 += BK) {
        // ---- load A tile (weights, L2-resident) ----
        #pragma unroll
        for (int i = 0; i < 8; i++)
            As[ak0 + i][am] = Arow[k0 + ak0 + i];
        // ---- load B tile (shifted x row, zero-pad W edges) ----
        {
            const int k  = k0 + bk;
            const int ci = k / 5;
            const int kk = k % 5;
            const float* __restrict__ xp = xrow + (size_t)ci * HW;
            #pragma unroll
            for (int j = 0; j < 4; j++) {
                const int wp = w0 + bn0 + j + kk - 2;
                Bs[bk][bn0 + j] = (wp >= 0 && wp < WW) ? xp[wp] : 0.f;
            }
        }
        __syncthreads();
        #pragma unroll
        for (int kq = 0; kq < BK; kq++) {
            const float4 a0 = *reinterpret_cast<const float4*>(&As[kq][ty * TM]);
            const float4 a1 = *reinterpret_cast<const float4*>(&As[kq][ty * TM + 4]);
            const float4 bb = *reinterpret_cast<const float4*>(&Bs[kq][tx * TN]);
            const float a[TM] = {a0.x, a0.y, a0.z, a0.w, a1.x, a1.y, a1.z, a1.w};
            const float bv[TN] = {bb.x, bb.y, bb.z, bb.w};
            #pragma unroll
            for (int i = 0; i < TM; i++)
                #pragma unroll
                for (int j = 0; j < TN; j++)
                    acc[i][j] += a[i] * bv[j];
        }
        __syncthreads();
    }

    // epilogue: NCHW, float4 along w
    #pragma unroll
    for (int i = 0; i < TM; i++) {
        const int co = co0 + ty * TM + i;
        const float bias = b15[co];
        float4 v;
        v.x = acc[i][0] + bias;
        v.y = acc[i][1] + bias;
        v.z = acc[i][2] + bias;
        v.w = acc[i][3] + bias;
        float* op = g_tmp + (size_t)(b * CCH + co) * HW + (size_t)h * WW + w0 + tx * TN;
        *reinterpret_cast<float4*>(op) = v;
    }
}

// ============================================================
// Kernel 2: feat = conv_5x1(tmp) + b51 + conv_1x1(x) + b11   (fused, K = 1536)
//   k <  1280 : A = w51 flat, B = tmp shifted along h (zero pad)
//   k >= 1280 : A = w11 flat, B = x
// Output NHWC for the align kernel.
// ============================================================
__global__ __launch_bounds__(256) void conv51_11_kernel(
    const float* __restrict__ x,
    const float* __restrict__ w51,
    const float* __restrict__ w11,
    const float* __restrict__ b51,
    const float* __restrict__ b11)
{
    const int nb = blockIdx.x;
    const int b  = nb / (HH * 3);
    const int r  = nb % (HH * 3);
    const int h  = r / 3;
    const int w0 = (r % 3) * BN;
    const int co0 = blockIdx.y * BM;

    __shared__ float As[BK][BM];
    __shared__ float Bs[BK][BN];

    const int tid = threadIdx.x;
    const int tx = tid % 16;
    const int ty = tid / 16;
    float acc[TM][TN] = {};

    const int am  = tid % BM;
    const int ak0 = (tid / BM) * 8;
    const float* __restrict__ A51 = w51 + (size_t)(co0 + am) * (CCH * 5);
    const float* __restrict__ A11 = w11 + (size_t)(co0 + am) * CCH;

    const int bk  = tid / 16;
    const int bn0 = (tid % 16) * 4;

    const float* __restrict__ xb   = x     + (size_t)b * CHW;
    const float* __restrict__ tmpb = g_tmp + (size_t)b * CHW;

    const int KTOT = CCH * 5 + CCH;   // 1536

    for (int k0 = 0; k0 < KTOT; k0 += BK) {
        // ---- load A tile ----
        if (k0 + ak0 < CCH * 5) {
            #pragma unroll
            for (int i = 0; i < 8; i++)
                As[ak0 + i][am] = A51[k0 + ak0 + i];
        } else {
            #pragma unroll
            for (int i = 0; i < 8; i++)
                As[ak0 + i][am] = A11[k0 + ak0 + i - CCH * 5];
        }
        // ---- load B tile ----
        {
            const int k = k0 + bk;
            if (k < CCH * 5) {
                const int ci = k / 5;
                const int kk = k % 5;
                const int hp = h + kk - 2;
                if (hp >= 0 && hp < HH) {
                    const float* __restrict__ tp = tmpb + (size_t)ci * HW + (size_t)hp * WW + w0 + bn0;
                    *reinterpret_cast<float4*>(&Bs[bk][bn0]) =
                        *reinterpret_cast<const float4*>(tp);
                } else {
                    #pragma unroll
                    for (int j = 0; j < 4; j++) Bs[bk][bn0 + j] = 0.f;
                }
            } else {
                const int ci = k - CCH * 5;
                const float* __restrict__ xp = xb + (size_t)ci * HW + (size_t)h * WW + w0 + bn0;
                *reinterpret_cast<float4*>(&Bs[bk][bn0]) =
                    *reinterpret_cast<const float4*>(xp);
            }
        }
        __syncthreads();
        #pragma unroll
        for (int kq = 0; kq < BK; kq++) {
            const float4 a0 = *reinterpret_cast<const float4*>(&As[kq][ty * TM]);
            const float4 a1 = *reinterpret_cast<const float4*>(&As[kq][ty * TM + 4]);
            const float4 bb = *reinterpret_cast<const float4*>(&Bs[kq][tx * TN]);
            const float a[TM] = {a0.x, a0.y, a0.z, a0.w, a1.x, a1.y, a1.z, a1.w};
            const float bv[TN] = {bb.x, bb.y, bb.z, bb.w};
            #pragma unroll
            for (int i = 0; i < TM; i++)
                #pragma unroll
                for (int j = 0; j < TN; j++)
                    acc[i][j] += a[i] * bv[j];
        }
        __syncthreads();
    }

    // epilogue: NHWC, two float4s along co per pixel
    float bias[TM];
    #pragma unroll
    for (int i = 0; i < TM; i++) {
        const int co = co0 + ty * TM + i;
        bias[i] = b51[co] + b11[co];
    }
    #pragma unroll
    for (int j = 0; j < TN; j++) {
        const int pix = (b * HH + h) * WW + w0 + tx * TN + j;
        float* fp = g_feat + (size_t)pix * CCH + co0 + ty * TM;
        float4 v0, v1;
        v0.x = acc[0][j] + bias[0];
        v0.y = acc[1][j] + bias[1];
        v0.z = acc[2][j] + bias[2];
        v0.w = acc[3][j] + bias[3];
        v1.x = acc[4][j] + bias[4];
        v1.y = acc[5][j] + bias[5];
        v1.z = acc[6][j] + bias[6];
        v1.w = acc[7][j] + bias[7];
        reinterpret_cast<float4*>(fp)[0] = v0;
        reinterpret_cast<float4*>(fp)[1] = v1;
    }
}

// ============================================================
// Kernel 3: out = x + feat + bilinear(feat, box_center)
// feat is NHWC (coalesced channel rows for the 4 random corners);
// transpose through padded smem so NCHW x/out stay coalesced.
// Block = 32 pixels of one (b,h) row; 256 threads = channels.
// ============================================================
__global__ __launch_bounds__(256) void align_kernel(
    const float* __restrict__ x,
    const float* __restrict__ boxes,
    float* __restrict__ out)
{
    __shared__ float s[32][CCH + 1];   // +1 pad: conflict-free transpose

    const int nb = blockIdx.x;              // BATCH*HH*6
    const int b  = nb / (HH * 6);
    const int r  = nb % (HH * 6);
    const int h  = r / 6;
    const int w0 = (r % 6) * 32;
    const int c  = threadIdx.x;             // channel

    const float* __restrict__ featb = g_feat + (size_t)b * HW * CCH;
    const float scale = 0.125f;             // 1/STRIDE

    #pragma unroll 1
    for (int p = 0; p < 32; p++) {
        const int pix = h * WW + (w0 + p);
        const float* __restrict__ bx = boxes + ((size_t)b * HW + pix) * 5;
        float yv = bx[0] * scale;           // mmcv reads (y, x)
        float xv = bx[1] * scale;
        const bool valid = (yv >= -1.f) & (yv <= (float)HH) &
                           (xv >= -1.f) & (xv <= (float)WW);
        const float fc = featb[(size_t)pix * CCH + c];
        float v = 0.f;
        if (valid) {
            yv = fmaxf(yv, 0.f);
            xv = fmaxf(xv, 0.f);
            int yl = (int)floorf(yv);
            int xl = (int)floorf(xv);
            int yh, xh;
            if (yl >= HH - 1) { yl = HH - 1; yh = HH - 1; yv = (float)(HH - 1); }
            else              { yh = yl + 1; }
            if (xl >= WW - 1) { xl = WW - 1; xh = WW - 1; xv = (float)(WW - 1); }
            else              { xh = xl + 1; }
            const float ly = yv - (float)yl;
            const float lx = xv - (float)xl;
            const float hy = 1.f - ly;
            const float hx = 1.f - lx;
            const float f00 = featb[((size_t)yl * WW + xl) * CCH + c];
            const float f01 = featb[((size_t)yl * WW + xh) * CCH + c];
            const float f10 = featb[((size_t)yh * WW + xl) * CCH + c];
            const float f11 = featb[((size_t)yh * WW + xh) * CCH + c];
            v = hy * hx * f00 + hy * lx * f01 + ly * hx * f10 + ly * lx * f11;
        }
        s[p][c] = fc + v;
    }
    __syncthreads();

    // transpose write-out: warp owns 32 channels, lanes sweep pixels
    const int wid  = c / 32;
    const int lane = c % 32;
    const int w    = w0 + lane;
    #pragma unroll 1
    for (int i = 0; i < 32; i++) {
        const int cc = wid * 32 + i;
        const size_t gi = ((size_t)(b * CCH + cc) * HH + h) * WW + w;
        out[gi] = x[gi] + s[lane][cc];
    }
}

// ============================================================
// Launch: 3 graph-capturable kernels, no syncs, no allocs.
// Inputs (metadata order): x, best_rbboxes, w51, b51, w15, b15, w11, b11
// ============================================================
extern "C" void kernel_launch(void* const* d_in, const int* in_sizes, int n_in,
                              void* d_out, int out_size)
{
    const float* x     = (const float*)d_in[0];
    const float* boxes = (const float*)d_in[1];
    const float* w51   = (const float*)d_in[2];
    const float* b51   = (const float*)d_in[3];
    const float* w15   = (const float*)d_in[4];
    const float* b15   = (const float*)d_in[5];
    const float* w11   = (const float*)d_in[6];
    const float* b11   = (const float*)d_in[7];
    float* out = (float*)d_out;

    dim3 gemm_grid(BATCH * HH * 3, CCH / BM);   // 1152 x 2
    conv15_kernel   <<<gemm_grid, 256>>>(x, w15, b15);
    conv51_11_kernel<<<gemm_grid, 256>>>(x, w51, w11, b51, b11);
    align_kernel    <<<BATCH * HH * 6, 256>>>(x, boxes, out);
}

// round 8
// speedup vs baseline: 3.6106x; 3.6106x over previous
#include <cuda_runtime.h>
#include <cuda_bf16.h>
#include <cstdint>

// ---------------- problem constants ----------------
#define BATCH 2
#define CCH   256
#define HH    192
#define WW    192
#define HW    (HH * WW)            // 36864
#define NTOT  (BATCH * HW)         // 73728
#define WP    (WW + 4)             // 196
#define HP    (HH + 4)             // 196

// GEMM chunk geometry: CTA 128(co) x 96(pix), BK=16
#define NC1 80                     // K=1280 (conv1x5 / conv5x1)
#define NC2 96                     // K=1536 (conv5x1 + conv1x1)
#define CHUNK_A 2048               // floats per A chunk (16k x 128m), fragment-packed

// ---------------- device scratch ----------------
__device__ float g_xP  [BATCH * CCH * HH * WP];   // NCHW, w-padded(+2), tf32-rounded
__device__ float g_tmpP[BATCH * CCH * HP * WW];   // NCHW, h-padded(+2), tf32-rounded
__device__ float g_feat[BATCH * HH * WW * CCH];   // NHWC fp32
__device__ float g_w15P[2 * NC1 * CHUNK_A];       // fragment-packed w15
__device__ float g_w51P[2 * NC2 * CHUNK_A];       // fragment-packed w51 (+w11 tail)

// ---------------- helpers ----------------
// cvt.rna.tf32.f32 requires a .b32 destination register -> "=r" constraint
__device__ __forceinline__ float tf32r(float x) {
    uint32_t y;
    asm("cvt.rna.tf32.f32 %0, %1;" : "=r"(y) : "f"(x));
    return __uint_as_float(y);
}
__device__ __forceinline__ uint32_t smem_u32(const void* p) {
    uint32_t a;
    asm("{ .reg .u64 t; cvta.to.shared.u64 t, %1; cvt.u32.u64 %0, t; }" : "=r"(a) : "l"(p));
    return a;
}
#define CP_ASYNC16(dst, src) \
    asm volatile("cp.async.ca.shared.global [%0], [%1], 16;" :: "r"(dst), "l"(src))
#define CP_ASYNC4(dst, src) \
    asm volatile("cp.async.ca.shared.global [%0], [%1], 4;" :: "r"(dst), "l"(src))
#define CP_COMMIT()  asm volatile("cp.async.commit_group;")
#define CP_WAIT_1()  asm volatile("cp.async.wait_group 1;")
#define CP_WAIT_0()  asm volatile("cp.async.wait_group 0;")

__device__ __forceinline__ void mma_tf32(float* d, const uint32_t* a, const uint32_t* b) {
    asm volatile(
        "mma.sync.aligned.m16n8k8.row.col.f32.tf32.tf32.f32 "
        "{%0,%1,%2,%3}, {%4,%5,%6,%7}, {%8,%9}, {%0,%1,%2,%3};"
        : "+f"(d[0]), "+f"(d[1]), "+f"(d[2]), "+f"(d[3])
        : "r"(a[0]), "r"(a[1]), "r"(a[2]), "r"(a[3]), "r"(b[0]), "r"(b[1]));
}

// ---------------- prep kernels ----------------
__global__ void pad_x_kernel(const float* __restrict__ x) {
    const int N = BATCH * CCH * HH * WP;
    for (int id = blockIdx.x * blockDim.x + threadIdx.x; id < N;
         id += gridDim.x * blockDim.x) {
        int wp = id % WP, t = id / WP;
        int h = t % HH;  t /= HH;        // t = b*CCH + c
        float v = 0.f;
        if (wp >= 2 && wp < WW + 2)
            v = tf32r(x[((size_t)t * HH + h) * WW + (wp - 2)]);
        g_xP[id] = v;
    }
}

__global__ void zero_tmp_kernel() {
    const int N = BATCH * CCH * 4 * WW;
    for (int id = blockIdx.x * blockDim.x + threadIdx.x; id < N;
         id += gridDim.x * blockDim.x) {
        int w = id % WW, t = id / WW;
        int hs = t % 4,  bc = t / 4;
        int hpos = (hs < 2) ? hs : (hs + HH);
        g_tmpP[((size_t)bc * HP + hpos) * WW + w] = 0.f;
    }
}

// fragment-pack weights: per (cb, c, k8b, wm, mi, lane, reg)
//   m = wm*64 + mi*16 + (lane>>2) + (reg&1)*8
//   k = k8b*8 + (lane&3) + (reg>>1)*4
// w15P from w15[co][ci][kk] (gk=c*16+k; ci=gk/5, kk=gk%5)
// w51P from w51 for gk<1280, else w11[co][gk-1280]
__global__ void wpack_kernel(const float* __restrict__ w15,
                             const float* __restrict__ w51,
                             const float* __restrict__ w11) {
    const int N2 = 2 * NC2 * CHUNK_A;     // 393216
    for (int id = blockIdx.x * blockDim.x + threadIdx.x; id < N2;
         id += gridDim.x * blockDim.x) {
        int reg  = id & 3;
        int lane = (id >> 2) & 31;
        int mi   = (id >> 7) & 3;
        int wm   = (id >> 9) & 1;
        int k8b  = (id >> 10) & 1;
        int rest = id >> 11;              // cb*NC2 + c
        int m_local = wm * 64 + mi * 16 + (lane >> 2) + (reg & 1) * 8;
        int k_local = k8b * 8 + (lane & 3) + (reg >> 1) * 4;
        int c  = rest % NC2;
        int cb = rest / NC2;
        int co = cb * 128 + m_local;
        int gk = c * 16 + k_local;
        float v;
        if (gk < 1280) {
            int ci = gk / 5, kk = gk % 5;
            v = tf32r(w51[(co * CCH + ci) * 5 + kk]);
        } else {
            v = tf32r(w11[co * CCH + (gk - 1280)]);
        }
        g_w51P[id] = v;
    }
    const int N1 = 2 * NC1 * CHUNK_A;     // 327680
    for (int id = blockIdx.x * blockDim.x + threadIdx.x; id < N1;
         id += gridDim.x * blockDim.x) {
        int reg  = id & 3;
        int lane = (id >> 2) & 31;
        int mi   = (id >> 7) & 3;
        int wm   = (id >> 9) & 1;
        int k8b  = (id >> 10) & 1;
        int rest = id >> 11;
        int c  = rest % NC1;
        int cb = rest / NC1;
        int m_local = wm * 64 + mi * 16 + (lane >> 2) + (reg & 1) * 8;
        int k_local = k8b * 8 + (lane & 3) + (reg >> 1) * 4;
        int co = cb * 128 + m_local;
        int gk = c * 16 + k_local;
        int ci = gk / 5, kk = gk % 5;
        g_w15P[id] = tf32r(w15[(co * CCH + ci) * 5 + kk]);
    }
}

// ---------------- tf32 mma.sync GEMM ----------------
// smem stage: A packed 8192B + B packed 6144B, double buffered
#define A_BYTES 8192
#define B_BYTES 6144
#define STAGE_BYTES (A_BYTES + B_BYTES)

__global__ __launch_bounds__(256, 2) void gemm_mma(
    int mode,
    const float* __restrict__ bias1,
    const float* __restrict__ bias2)
{
    __shared__ __align__(16) char smem[2 * STAGE_BYTES];
    const uint32_t sbase = smem_u32(smem);

    const int tid  = threadIdx.x;
    const int lane = tid & 31;
    const int warp = tid >> 5;
    const int wm = warp >> 2;          // 0..1
    const int wn = warp & 3;           // 0..3
    const int m0 = wm * 64;
    const int n0 = wn * 24;
    const int g  = lane >> 2;          // 0..7
    const int tq = lane & 3;           // 0..3

    const int p0 = blockIdx.x * 96;
    const int b  = p0 / HW;
    const int rr = p0 % HW;
    const int h  = rr / WW;
    const int w0 = rr % WW;            // 0 or 96
    const int cb = blockIdx.y;
    const int co0 = cb * 128;

    const int NC = (mode == 1) ? NC1 : NC2;
    const float* __restrict__ wsrc =
        (mode == 1) ? (g_w15P + (size_t)cb * NC1 * CHUNK_A)
                    : (g_w51P + (size_t)cb * NC2 * CHUNK_A);

    float acc[4][3][4];
    #pragma unroll
    for (int mi = 0; mi < 4; mi++)
        #pragma unroll
        for (int ni = 0; ni < 3; ni++)
            #pragma unroll
            for (int q = 0; q < 4; q++) acc[mi][ni][q] = 0.f;

    auto issue_load = [&](int c, int st) {
        const uint32_t sA = sbase + st * STAGE_BYTES;
        const uint32_t sB = sA + A_BYTES;
        // A: linear 16B-aligned copy of fragment-packed chunk (512 x 16B)
        const float* asrc = wsrc + (size_t)c * CHUNK_A;
        #pragma unroll
        for (int r = 0; r < 2; r++) {
            int s = tid + r * 256;
            CP_ASYNC16(sA + (uint32_t)s * 16, asrc + s * 4);
        }
        // B: 1536 floats, 4B cp.async scattered into packed layout [k8][col][tq][2]
        #pragma unroll
        for (int r = 0; r < 6; r++) {
            int s = tid + r * 256;          // 0..1535
            int k = s / 96, col = s % 96;
            int k8b = k >> 3, kl = k & 7;
            uint32_t dstf = (uint32_t)(((k8b * 96 + col) * 4 + (kl & 3)) * 2 + (kl >> 2));
            const float* src;
            if (mode == 1) {
                int gk = c * 16 + k;
                int ci = gk / 5, kw = gk % 5;
                src = g_xP + ((size_t)(b * CCH + ci) * HH + h) * WP + w0 + kw + col;
            } else if (c < NC1) {
                int gk = c * 16 + k;
                int ci = gk / 5, kh = gk % 5;
                src = g_tmpP + ((size_t)(b * CCH + ci) * HP + h + kh) * WW + w0 + col;
            } else {
                int ci = (c - NC1) * 16 + k;
                src = g_xP + ((size_t)(b * CCH + ci) * HH + h) * WP + w0 + 2 + col;
            }
            CP_ASYNC4(sB + dstf * 4, src);
        }
        CP_COMMIT();
    };

    issue_load(0, 0);

    for (int c = 0; c < NC; c++) {
        if (c + 1 < NC) { issue_load(c + 1, (c + 1) & 1); CP_WAIT_1(); }
        else           { CP_WAIT_0(); }
        __syncthreads();

        const char* As = smem + (c & 1) * STAGE_BYTES;
        const char* Bs = As + A_BYTES;

        #pragma unroll
        for (int k8b = 0; k8b < 2; k8b++) {
            uint32_t afr[4][4];
            #pragma unroll
            for (int mi = 0; mi < 4; mi++) {
                const uint4 va = *reinterpret_cast<const uint4*>(
                    As + ((((k8b * 2 + wm) * 4 + mi) * 32 + lane) << 4));
                afr[mi][0] = va.x; afr[mi][1] = va.y;
                afr[mi][2] = va.z; afr[mi][3] = va.w;
            }
            #pragma unroll
            for (int ni = 0; ni < 3; ni++) {
                const int nc = n0 + ni * 8 + g;
                const uint2 vb = *reinterpret_cast<const uint2*>(
                    Bs + (((k8b * 96 + nc) * 4 + tq) << 3));
                uint32_t bfr[2] = {vb.x, vb.y};
                #pragma unroll
                for (int mi = 0; mi < 4; mi++)
                    mma_tf32(acc[mi][ni], afr[mi], bfr);
            }
        }
        __syncthreads();
    }

    // ---- epilogue ----
    if (mode == 1) {
        #pragma unroll
        for (int mi = 0; mi < 4; mi++) {
            const int coA = co0 + m0 + mi * 16 + g;
            const float bA = bias1[coA];
            const float bB = bias1[coA + 8];
            #pragma unroll
            for (int ni = 0; ni < 3; ni++) {
                const int w = w0 + n0 + ni * 8 + tq * 2;
                float2 vA = make_float2(tf32r(acc[mi][ni][0] + bA),
                                        tf32r(acc[mi][ni][1] + bA));
                float2 vB = make_float2(tf32r(acc[mi][ni][2] + bB),
                                        tf32r(acc[mi][ni][3] + bB));
                size_t rA = ((size_t)(b * CCH + coA) * HP + h + 2) * WW + w;
                size_t rB = ((size_t)(b * CCH + coA + 8) * HP + h + 2) * WW + w;
                *reinterpret_cast<float2*>(g_tmpP + rA) = vA;
                *reinterpret_cast<float2*>(g_tmpP + rB) = vB;
            }
        }
    } else {
        float* s = (float*)smem;                 // [24 pix][132]
        for (int j = 0; j < 4; j++) {
            __syncthreads();
            if (wn == j) {
                #pragma unroll
                for (int mi = 0; mi < 4; mi++) {
                    const int clA = m0 + mi * 16 + g;
                    const float bA = bias1[co0 + clA] + bias2[co0 + clA];
                    const float bB = bias1[co0 + clA + 8] + bias2[co0 + clA + 8];
                    #pragma unroll
                    for (int ni = 0; ni < 3; ni++) {
                        const int nc = ni * 8 + tq * 2;
                        s[nc * 132 + clA]           = acc[mi][ni][0] + bA;
                        s[(nc + 1) * 132 + clA]     = acc[mi][ni][1] + bA;
                        s[nc * 132 + clA + 8]       = acc[mi][ni][2] + bB;
                        s[(nc + 1) * 132 + clA + 8] = acc[mi][ni][3] + bB;
                    }
                }
            }
            __syncthreads();
            #pragma unroll
            for (int r = 0; r < 3; r++) {
                int slot = r * 256 + tid;          // 768 = 24 x 32
                int p = slot >> 5, gg = slot & 31;
                float4 v = *reinterpret_cast<float4*>(&s[p * 132 + gg * 4]);
                size_t dst = ((size_t)(b * HH + h) * WW + w0 + j * 24 + p) * CCH
                           + co0 + gg * 4;
                *reinterpret_cast<float4*>(g_feat + dst) = v;
            }
        }
    }
}

// ---------------- align + residual (passed R2) ----------------
__global__ __launch_bounds__(256) void align_kernel(
    const float* __restrict__ x,
    const float* __restrict__ boxes,
    float* __restrict__ out)
{
    __shared__ float s[32][CCH + 1];
    const int nb = blockIdx.x;
    const int b  = nb / (HH * 6);
    const int r  = nb % (HH * 6);
    const int h  = r / 6;
    const int w0 = (r % 6) * 32;
    const int c  = threadIdx.x;
    const float* __restrict__ featb = g_feat + (size_t)b * HW * CCH;
    const float scale = 0.125f;

    #pragma unroll 1
    for (int p = 0; p < 32; p++) {
        const int pix = h * WW + (w0 + p);
        const float* __restrict__ bx = boxes + ((size_t)b * HW + pix) * 5;
        float yv = bx[0] * scale;
        float xv = bx[1] * scale;
        const bool valid = (yv >= -1.f) & (yv <= (float)HH) &
                           (xv >= -1.f) & (xv <= (float)WW);
        const float fc = featb[(size_t)pix * CCH + c];
        float v = 0.f;
        if (valid) {
            yv = fmaxf(yv, 0.f);
            xv = fmaxf(xv, 0.f);
            int yl = (int)floorf(yv);
            int xl = (int)floorf(xv);
            int yh, xh;
            if (yl >= HH - 1) { yl = HH - 1; yh = HH - 1; yv = (float)(HH - 1); }
            else              { yh = yl + 1; }
            if (xl >= WW - 1) { xl = WW - 1; xh = WW - 1; xv = (float)(WW - 1); }
            else              { xh = xl + 1; }
            const float ly = yv - (float)yl;
            const float lx = xv - (float)xl;
            const float hy = 1.f - ly;
            const float hx = 1.f - lx;
            const float f00 = featb[((size_t)yl * WW + xl) * CCH + c];
            const float f01 = featb[((size_t)yl * WW + xh) * CCH + c];
            const float f10 = featb[((size_t)yh * WW + xl) * CCH + c];
            const float f11 = featb[((size_t)yh * WW + xh) * CCH + c];
            v = hy * hx * f00 + hy * lx * f01 + ly * hx * f10 + ly * lx * f11;
        }
        s[p][c] = fc + v;
    }
    __syncthreads();
    const int wid = c / 32, lane = c % 32;
    const int w = w0 + lane;
    #pragma unroll 1
    for (int i = 0; i < 32; i++) {
        const int cc = wid * 32 + i;
        const size_t gi = ((size_t)(b * CCH + cc) * HH + h) * WW + w;
        out[gi] = x[gi] + s[lane][cc];
    }
}

// ---------------- launch ----------------
extern "C" void kernel_launch(void* const* d_in, const int* in_sizes, int n_in,
                              void* d_out, int out_size)
{
    const float* x     = (const float*)d_in[0];
    const float* boxes = (const float*)d_in[1];
    const float* w51   = (const float*)d_in[2];
    const float* b51   = (const float*)d_in[3];
    const float* w15   = (const float*)d_in[4];
    const float* b15   = (const float*)d_in[5];
    const float* w11   = (const float*)d_in[6];
    const float* b11   = (const float*)d_in[7];
    float* out = (float*)d_out;

    pad_x_kernel   <<<2048, 256>>>(x);
    zero_tmp_kernel<<<512, 256>>>();
    wpack_kernel   <<<768, 256>>>(w15, w51, w11);

    dim3 gg(NTOT / 96, 2);   // 768 x 2
    gemm_mma<<<gg, 256>>>(1, b15, b15);
    gemm_mma<<<gg, 256>>>(2, b51, b11);

    align_kernel<<<BATCH * HH * 6, 256>>>(x, boxes, out);
}

// round 9
// speedup vs baseline: 5.1797x; 1.4346x over previous
#include <cuda_runtime.h>
#include <cuda_bf16.h>
#include <cstdint>

// ---------------- problem constants ----------------
#define BATCH 2
#define CCH   256
#define HH    192
#define WW    192
#define HW    (HH * WW)            // 36864
#define NTOT  (BATCH * HW)         // 73728
#define WP    (WW + 4)             // 196
#define HP    (HH + 4)             // 196

// GEMM chunk geometry: CTA 128(co) x 96(pix), BK=16
#define NC1 80                     // K=1280
#define NC2 96                     // K=1536
#define CHUNK_A 2048               // floats per A chunk, fragment-packed

// ---------------- device scratch ----------------
__device__ float g_xP  [BATCH * CCH * HH * WP + 64]; // NCHW w-padded(+2) tf32; +64 slack for superset reads
__device__ float g_xC  [BATCH * CCH * HH * WW];      // NCHW plain tf32 (for 1x1, 16B-aligned rows)
__device__ float g_tmpP[BATCH * CCH * HP * WW];      // NCHW h-padded(+2) tf32
__device__ float g_feat[BATCH * HH * WW * CCH];      // NHWC fp32
__device__ float g_w15P[2 * NC1 * CHUNK_A];          // fragment-packed w15 (kw-major K)
__device__ float g_w51P[2 * NC2 * CHUNK_A];          // fragment-packed w51 (kh-major) + w11 tail

// ---------------- helpers ----------------
__device__ __forceinline__ float tf32r(float x) {
    uint32_t y;
    asm("cvt.rna.tf32.f32 %0, %1;" : "=r"(y) : "f"(x));
    return __uint_as_float(y);
}
__device__ __forceinline__ uint32_t smem_u32(const void* p) {
    uint32_t a;
    asm("{ .reg .u64 t; cvta.to.shared.u64 t, %1; cvt.u32.u64 %0, t; }" : "=r"(a) : "l"(p));
    return a;
}
#define CP_ASYNC16(dst, src) \
    asm volatile("cp.async.ca.shared.global [%0], [%1], 16;" :: "r"(dst), "l"(src))
#define CP_COMMIT()  asm volatile("cp.async.commit_group;")
#define CP_WAIT_1()  asm volatile("cp.async.wait_group 1;")
#define CP_WAIT_0()  asm volatile("cp.async.wait_group 0;")

__device__ __forceinline__ void mma_tf32(float* d, const uint32_t* a, const uint32_t* b) {
    asm volatile(
        "mma.sync.aligned.m16n8k8.row.col.f32.tf32.tf32.f32 "
        "{%0,%1,%2,%3}, {%4,%5,%6,%7}, {%8,%9}, {%0,%1,%2,%3};"
        : "+f"(d[0]), "+f"(d[1]), "+f"(d[2]), "+f"(d[3])
        : "r"(a[0]), "r"(a[1]), "r"(a[2]), "r"(a[3]), "r"(b[0]), "r"(b[1]));
}

// ---------------- prep kernels ----------------
__global__ void pad_x_kernel(const float* __restrict__ x) {
    const int N = BATCH * CCH * HH * WP;
    for (int id = blockIdx.x * blockDim.x + threadIdx.x; id < N;
         id += gridDim.x * blockDim.x) {
        int wp = id % WP, t = id / WP;
        int h = t % HH;  t /= HH;        // t = b*CCH + c
        float v = 0.f;
        if (wp >= 2 && wp < WW + 2)
            v = tf32r(x[((size_t)t * HH + h) * WW + (wp - 2)]);
        g_xP[id] = v;
    }
    const int N2 = BATCH * CCH * HW;
    for (int id = blockIdx.x * blockDim.x + threadIdx.x; id < N2;
         id += gridDim.x * blockDim.x)
        g_xC[id] = tf32r(x[id]);
}

__global__ void zero_tmp_kernel() {
    const int N = BATCH * CCH * 4 * WW;
    for (int id = blockIdx.x * blockDim.x + threadIdx.x; id < N;
         id += gridDim.x * blockDim.x) {
        int w = id % WW, t = id / WW;
        int hs = t % 4,  bc = t / 4;
        int hpos = (hs < 2) ? hs : (hs + HH);
        g_tmpP[((size_t)bc * HP + hpos) * WW + w] = 0.f;
    }
}

// fragment-pack weights, K reordered SHIFT-MAJOR: gk = kw*256 + ci
//   m = wm*64 + mi*16 + (lane>>2) + (reg&1)*8
//   k = k8b*8 + (lane&3) + (reg>>1)*4
__global__ void wpack_kernel(const float* __restrict__ w15,
                             const float* __restrict__ w51,
                             const float* __restrict__ w11) {
    const int N2 = 2 * NC2 * CHUNK_A;
    for (int id = blockIdx.x * blockDim.x + threadIdx.x; id < N2;
         id += gridDim.x * blockDim.x) {
        int reg  = id & 3;
        int lane = (id >> 2) & 31;
        int mi   = (id >> 7) & 3;
        int wm   = (id >> 9) & 1;
        int k8b  = (id >> 10) & 1;
        int rest = id >> 11;              // cb*NC2 + c
        int m_local = wm * 64 + mi * 16 + (lane >> 2) + (reg & 1) * 8;
        int k_local = k8b * 8 + (lane & 3) + (reg >> 1) * 4;
        int c  = rest % NC2;
        int cb = rest / NC2;
        int co = cb * 128 + m_local;
        int gk = c * 16 + k_local;
        float v;
        if (gk < 1280) {
            int kh = gk >> 8, ci = gk & 255;
            v = tf32r(w51[(co * CCH + ci) * 5 + kh]);
        } else {
            v = tf32r(w11[co * CCH + (gk - 1280)]);
        }
        g_w51P[id] = v;
    }
    const int N1 = 2 * NC1 * CHUNK_A;
    for (int id = blockIdx.x * blockDim.x + threadIdx.x; id < N1;
         id += gridDim.x * blockDim.x) {
        int reg  = id & 3;
        int lane = (id >> 2) & 31;
        int mi   = (id >> 7) & 3;
        int wm   = (id >> 9) & 1;
        int k8b  = (id >> 10) & 1;
        int rest = id >> 11;
        int c  = rest % NC1;
        int cb = rest / NC1;
        int m_local = wm * 64 + mi * 16 + (lane >> 2) + (reg & 1) * 8;
        int k_local = k8b * 8 + (lane & 3) + (reg >> 1) * 4;
        int co = cb * 128 + m_local;
        int gk = c * 16 + k_local;
        int kw = gk >> 8, ci = gk & 255;
        g_w15P[id] = tf32r(w15[(co * CCH + ci) * 5 + kw]);
    }
}

// ---------------- tf32 mma.sync GEMM ----------------
// smem stage: A packed 8192B + B row-major 16 x 104 floats (6656B); 3 stages
#define A_BYTES 8192
#define BSTRIDE 104                 // floats; 104 % 32 == 8 -> conflict-free B reads
#define B_BYTES (16 * BSTRIDE * 4)  // 6656
#define STAGE_BYTES (A_BYTES + B_BYTES)   // 14848
#define NSTG 3

__global__ __launch_bounds__(256, 2) void gemm_mma(
    int mode,
    const float* __restrict__ bias1,
    const float* __restrict__ bias2)
{
    __shared__ __align__(16) char smem[NSTG * STAGE_BYTES];
    const uint32_t sbase = smem_u32(smem);

    const int tid  = threadIdx.x;
    const int lane = tid & 31;
    const int warp = tid >> 5;
    const int wm = warp >> 2;          // 0..1
    const int wn = warp & 3;           // 0..3
    const int m0 = wm * 64;
    const int n0 = wn * 24;
    const int g  = lane >> 2;          // 0..7
    const int tq = lane & 3;           // 0..3

    const int p0 = blockIdx.x * 96;
    const int b  = p0 / HW;
    const int rr = p0 % HW;
    const int h  = rr / WW;
    const int w0 = rr % WW;            // 0 or 96
    const int cb = blockIdx.y;
    const int co0 = cb * 128;

    const int NC = (mode == 1) ? NC1 : NC2;
    const float* __restrict__ wsrc =
        (mode == 1) ? (g_w15P + (size_t)cb * NC1 * CHUNK_A)
                    : (g_w51P + (size_t)cb * NC2 * CHUNK_A);

    float acc[4][3][4];
    #pragma unroll
    for (int mi = 0; mi < 4; mi++)
        #pragma unroll
        for (int ni = 0; ni < 3; ni++)
            #pragma unroll
            for (int q = 0; q < 4; q++) acc[mi][ni][q] = 0.f;

    // loader: chunk c -> stage (A linear copy; B 16 aligned row supersets)
    auto issue_load = [&](int c) {
        const uint32_t sA = sbase + (c % NSTG) * STAGE_BYTES;
        const uint32_t sB = sA + A_BYTES;
        const float* asrc = wsrc + (size_t)c * CHUNK_A;
        #pragma unroll
        for (int r = 0; r < 2; r++) {
            int s = tid + r * 256;
            CP_ASYNC16(sA + (uint32_t)s * 16, asrc + s * 4);
        }
        // B rows: decode once per chunk
        const float* base;
        int rsg;                       // row stride (floats) between ci planes
        bool full25;                   // mode1 loads 25 slots/row, else 24
        if (mode == 1) {
            int kw = c >> 4, ci0 = (c & 15) << 4;
            base = g_xP + ((size_t)(b * CCH + ci0) * HH + h) * WP + w0 + (kw & ~3);
            rsg = HH * WP; full25 = true;
        } else if (c < NC1) {
            int kh = c >> 4, ci0 = (c & 15) << 4;
            base = g_tmpP + ((size_t)(b * CCH + ci0) * HP + (h + kh)) * WW + w0;
            rsg = HP * WW; full25 = false;
        } else {
            int ci0 = (c - NC1) << 4;
            base = g_xC + ((size_t)(b * CCH + ci0) * HH + h) * WW + w0;
            rsg = HH * WW; full25 = false;
        }
        #pragma unroll
        for (int r = 0; r < 2; r++) {
            int s = tid + r * 256;          // slots: row = s/25, slot = s%25
            if (s < 400) {
                int row = s / 25, slot = s - row * 25;
                if (full25 || slot < 24)
                    CP_ASYNC16(sB + (uint32_t)(row * BSTRIDE + slot * 4) * 4,
                               base + (size_t)row * rsg + slot * 4);
            }
        }
        CP_COMMIT();
    };

    issue_load(0);
    issue_load(1);

    for (int c = 0; c < NC; c++) {
        if (c + 1 < NC) { CP_WAIT_1(); } else { CP_WAIT_0(); }
        __syncthreads();

        const char* As = smem + (c % NSTG) * STAGE_BYTES;
        const float* Bs = (const float*)(As + A_BYTES);
        const int off0 = (mode == 1) ? ((c >> 4) & 3) : 0;

        #pragma unroll
        for (int k8b = 0; k8b < 2; k8b++) {
            uint32_t afr[4][4];
            #pragma unroll
            for (int mi = 0; mi < 4; mi++) {
                const uint4 va = *reinterpret_cast<const uint4*>(
                    As + ((((k8b * 2 + wm) * 4 + mi) * 32 + lane) << 4));
                afr[mi][0] = va.x; afr[mi][1] = va.y;
                afr[mi][2] = va.z; afr[mi][3] = va.w;
            }
            #pragma unroll
            for (int ni = 0; ni < 3; ni++) {
                const int nc = off0 + n0 + ni * 8 + g;
                uint32_t bfr[2];
                bfr[0] = __float_as_uint(Bs[(k8b * 8 + tq) * BSTRIDE + nc]);
                bfr[1] = __float_as_uint(Bs[(k8b * 8 + tq + 4) * BSTRIDE + nc]);
                #pragma unroll
                for (int mi = 0; mi < 4; mi++)
                    mma_tf32(acc[mi][ni], afr[mi], bfr);
            }
        }
        if (c + 2 < NC) issue_load(c + 2);   // overwrites stage (c+2)%3 = (c-1)%3: 2 barriers old -> safe
    }
    __syncthreads();

    // ---- epilogue ----
    if (mode == 1) {
        #pragma unroll
        for (int mi = 0; mi < 4; mi++) {
            const int coA = co0 + m0 + mi * 16 + g;
            const float bA = bias1[coA];
            const float bB = bias1[coA + 8];
            #pragma unroll
            for (int ni = 0; ni < 3; ni++) {
                const int w = w0 + n0 + ni * 8 + tq * 2;
                float2 vA = make_float2(tf32r(acc[mi][ni][0] + bA),
                                        tf32r(acc[mi][ni][1] + bA));
                float2 vB = make_float2(tf32r(acc[mi][ni][2] + bB),
                                        tf32r(acc[mi][ni][3] + bB));
                size_t rA = ((size_t)(b * CCH + coA) * HP + h + 2) * WW + w;
                size_t rB = ((size_t)(b * CCH + coA + 8) * HP + h + 2) * WW + w;
                *reinterpret_cast<float2*>(g_tmpP + rA) = vA;
                *reinterpret_cast<float2*>(g_tmpP + rB) = vB;
            }
        }
    } else {
        float* s = (float*)smem;                 // [24 pix][132]
        for (int j = 0; j < 4; j++) {
            __syncthreads();
            if (wn == j) {
                #pragma unroll
                for (int mi = 0; mi < 4; mi++) {
                    const int clA = m0 + mi * 16 + g;
                    const float bA = bias1[co0 + clA] + bias2[co0 + clA];
                    const float bB = bias1[co0 + clA + 8] + bias2[co0 + clA + 8];
                    #pragma unroll
                    for (int ni = 0; ni < 3; ni++) {
                        const int nc = ni * 8 + tq * 2;
                        s[nc * 132 + clA]           = acc[mi][ni][0] + bA;
                        s[(nc + 1) * 132 + clA]     = acc[mi][ni][1] + bA;
                        s[nc * 132 + clA + 8]       = acc[mi][ni][2] + bB;
                        s[(nc + 1) * 132 + clA + 8] = acc[mi][ni][3] + bB;
                    }
                }
            }
            __syncthreads();
            #pragma unroll
            for (int r = 0; r < 3; r++) {
                int slot = r * 256 + tid;          // 768 = 24 x 32
                int p = slot >> 5, gg = slot & 31;
                float4 v = *reinterpret_cast<float4*>(&s[p * 132 + gg * 4]);
                size_t dst = ((size_t)(b * HH + h) * WW + w0 + j * 24 + p) * CCH
                           + co0 + gg * 4;
                *reinterpret_cast<float4*>(g_feat + dst) = v;
            }
        }
    }
}

// ---------------- align + residual ----------------
__global__ __launch_bounds__(256) void align_kernel(
    const float* __restrict__ x,
    const float* __restrict__ boxes,
    float* __restrict__ out)
{
    __shared__ float s[32][CCH + 1];
    const int nb = blockIdx.x;
    const int b  = nb / (HH * 6);
    const int r  = nb % (HH * 6);
    const int h  = r / 6;
    const int w0 = (r % 6) * 32;
    const int c  = threadIdx.x;
    const float* __restrict__ featb = g_feat + (size_t)b * HW * CCH;
    const float scale = 0.125f;

    #pragma unroll 1
    for (int p = 0; p < 32; p++) {
        const int pix = h * WW + (w0 + p);
        const float* __restrict__ bx = boxes + ((size_t)b * HW + pix) * 5;
        float yv = bx[0] * scale;
        float xv = bx[1] * scale;
        const bool valid = (yv >= -1.f) & (yv <= (float)HH) &
                           (xv >= -1.f) & (xv <= (float)WW);
        const float fc = featb[(size_t)pix * CCH + c];
        float v = 0.f;
        if (valid) {
            yv = fmaxf(yv, 0.f);
            xv = fmaxf(xv, 0.f);
            int yl = (int)floorf(yv);
            int xl = (int)floorf(xv);
            int yh, xh;
            if (yl >= HH - 1) { yl = HH - 1; yh = HH - 1; yv = (float)(HH - 1); }
            else              { yh = yl + 1; }
            if (xl >= WW - 1) { xl = WW - 1; xh = WW - 1; xv = (float)(WW - 1); }
            else              { xh = xl + 1; }
            const float ly = yv - (float)yl;
            const float lx = xv - (float)xl;
            const float hy = 1.f - ly;
            const float hx = 1.f - lx;
            const float f00 = featb[((size_t)yl * WW + xl) * CCH + c];
            const float f01 = featb[((size_t)yl * WW + xh) * CCH + c];
            const float f10 = featb[((size_t)yh * WW + xl) * CCH + c];
            const float f11 = featb[((size_t)yh * WW + xh) * CCH + c];
            v = hy * hx * f00 + hy * lx * f01 + ly * hx * f10 + ly * lx * f11;
        }
        s[p][c] = fc + v;
    }
    __syncthreads();
    const int wid = c / 32, lane = c % 32;
    const int w = w0 + lane;
    #pragma unroll 1
    for (int i = 0; i < 32; i++) {
        const int cc = wid * 32 + i;
        const size_t gi = ((size_t)(b * CCH + cc) * HH + h) * WW + w;
        out[gi] = x[gi] + s[lane][cc];
    }
}

// ---------------- launch ----------------
extern "C" void kernel_launch(void* const* d_in, const int* in_sizes, int n_in,
                              void* d_out, int out_size)
{
    const float* x     = (const float*)d_in[0];
    const float* boxes = (const float*)d_in[1];
    const float* w51   = (const float*)d_in[2];
    const float* b51   = (const float*)d_in[3];
    const float* w15   = (const float*)d_in[4];
    const float* b15   = (const float*)d_in[5];
    const float* w11   = (const float*)d_in[6];
    const float* b11   = (const float*)d_in[7];
    float* out = (float*)d_out;

    pad_x_kernel   <<<2048, 256>>>(x);
    zero_tmp_kernel<<<512, 256>>>();
    wpack_kernel   <<<768, 256>>>(w15, w51, w11);

    dim3 gg(NTOT / 96, 2);   // 768 x 2
    gemm_mma<<<gg, 256>>>(1, b15, b15);
    gemm_mma<<<gg, 256>>>(2, b51, b11);

    align_kernel<<<BATCH * HH * 6, 256>>>(x, boxes, out);
}

// round 10
// speedup vs baseline: 5.7026x; 1.1010x over previous
#include <cuda_runtime.h>
#include <cuda_bf16.h>
#include <cstdint>

// ---------------- problem constants ----------------
#define BATCH 2
#define CCH   256
#define HH    192
#define WW    192
#define HW    (HH * WW)            // 36864
#define NTOT  (BATCH * HW)         // 73728
#define WP    (WW + 4)             // 196
#define HP    (HH + 4)             // 196

// GEMM chunk geometry: CTA 128(co) x 96(pix), BK=32
#define NC1 40                     // K=1280
#define NC2 48                     // K=1536
#define CHUNK_A 4096               // floats per A chunk (32k x 128m), fragment-packed

// ---------------- device scratch ----------------
__device__ float g_xP  [BATCH * CCH * HH * WP + 64]; // NCHW w-padded(+2) tf32 (+slack)
__device__ float g_xC  [BATCH * CCH * HH * WW];      // NCHW plain tf32 (1x1 path)
__device__ float g_tmpP[BATCH * CCH * HP * WW];      // NCHW h-padded(+2) tf32
__device__ float g_feat[BATCH * HH * WW * CCH];      // NHWC fp32
__device__ float g_w15P[2 * NC1 * CHUNK_A];          // fragment-packed w15 (kw-major K)
__device__ float g_w51P[2 * NC2 * CHUNK_A];          // fragment-packed w51 (kh-major) + w11 tail

// ---------------- helpers ----------------
__device__ __forceinline__ float tf32r(float x) {
    uint32_t y;
    asm("cvt.rna.tf32.f32 %0, %1;" : "=r"(y) : "f"(x));
    return __uint_as_float(y);
}
__device__ __forceinline__ uint32_t smem_u32(const void* p) {
    uint32_t a;
    asm("{ .reg .u64 t; cvta.to.shared.u64 t, %1; cvt.u32.u64 %0, t; }" : "=r"(a) : "l"(p));
    return a;
}
#define CP_ASYNC16(dst, src) \
    asm volatile("cp.async.ca.shared.global [%0], [%1], 16;" :: "r"(dst), "l"(src))
#define CP_COMMIT()  asm volatile("cp.async.commit_group;")
#define CP_WAIT_1()  asm volatile("cp.async.wait_group 1;")
#define CP_WAIT_0()  asm volatile("cp.async.wait_group 0;")

__device__ __forceinline__ void mma_tf32(float* d, const uint32_t* a, const uint32_t* b) {
    asm volatile(
        "mma.sync.aligned.m16n8k8.row.col.f32.tf32.tf32.f32 "
        "{%0,%1,%2,%3}, {%4,%5,%6,%7}, {%8,%9}, {%0,%1,%2,%3};"
        : "+f"(d[0]), "+f"(d[1]), "+f"(d[2]), "+f"(d[3])
        : "r"(a[0]), "r"(a[1]), "r"(a[2]), "r"(a[3]), "r"(b[0]), "r"(b[1]));
}

// ---------------- prep kernels ----------------
// row-indexed pad (no div/mod): blockIdx walks rows, threadIdx = wp
__global__ __launch_bounds__(256) void pad_x_kernel(const float* __restrict__ x) {
    const int rows = BATCH * CCH * HH;
    const int wp = threadIdx.x;
    for (int row = blockIdx.x; row < rows; row += gridDim.x) {
        if (wp < WP) {
            float v = 0.f;
            if (wp >= 2 && wp < WW + 2)
                v = tf32r(x[(size_t)row * WW + (wp - 2)]);
            g_xP[(size_t)row * WP + wp] = v;
        }
    }
}

// vectorized tf32-rounded copy for the 1x1 path
__global__ __launch_bounds__(256) void xc_kernel(const float* __restrict__ x) {
    const int N4 = BATCH * CCH * HW / 4;
    for (int id = blockIdx.x * blockDim.x + threadIdx.x; id < N4;
         id += gridDim.x * blockDim.x) {
        float4 v = reinterpret_cast<const float4*>(x)[id];
        v.x = tf32r(v.x); v.y = tf32r(v.y); v.z = tf32r(v.z); v.w = tf32r(v.w);
        reinterpret_cast<float4*>(g_xC)[id] = v;
    }
}

__global__ void zero_tmp_kernel() {
    const int N = BATCH * CCH * 4 * WW;
    for (int id = blockIdx.x * blockDim.x + threadIdx.x; id < N;
         id += gridDim.x * blockDim.x) {
        int w = id % WW, t = id / WW;
        int hs = t % 4,  bc = t / 4;
        int hpos = (hs < 2) ? hs : (hs + HH);
        g_tmpP[((size_t)bc * HP + hpos) * WW + w] = 0.f;
    }
}

// fragment-pack weights, K shift-major (gk = kshift*256 + ci), BK=32 chunks
//   m = wm*64 + mi*16 + (lane>>2) + (reg&1)*8
//   k = k8b*8 + (lane&3) + (reg>>1)*4     (k8b 0..3)
__global__ void wpack_kernel(const float* __restrict__ w15,
                             const float* __restrict__ w51,
                             const float* __restrict__ w11) {
    const int N2 = 2 * NC2 * CHUNK_A;
    for (int id = blockIdx.x * blockDim.x + threadIdx.x; id < N2;
         id += gridDim.x * blockDim.x) {
        int reg  = id & 3;
        int lane = (id >> 2) & 31;
        int mi   = (id >> 7) & 3;
        int wm   = (id >> 9) & 1;
        int k8b  = (id >> 10) & 3;
        int rest = id >> 12;              // cb*NC2 + c
        int m_local = wm * 64 + mi * 16 + (lane >> 2) + ((reg & 1) << 3);
        int k_local = k8b * 8 + (lane & 3) + ((reg >> 1) << 2);
        int c  = rest % NC2;
        int cb = rest / NC2;
        int co = cb * 128 + m_local;
        int gk = c * 32 + k_local;
        float v;
        if (gk < 1280) {
            int kh = gk >> 8, ci = gk & 255;
            v = tf32r(w51[(co * CCH + ci) * 5 + kh]);
        } else {
            v = tf32r(w11[co * CCH + (gk - 1280)]);
        }
        g_w51P[id] = v;
    }
    const int N1 = 2 * NC1 * CHUNK_A;
    for (int id = blockIdx.x * blockDim.x + threadIdx.x; id < N1;
         id += gridDim.x * blockDim.x) {
        int reg  = id & 3;
        int lane = (id >> 2) & 31;
        int mi   = (id >> 7) & 3;
        int wm   = (id >> 9) & 1;
        int k8b  = (id >> 10) & 3;
        int rest = id >> 12;
        int c  = rest % NC1;
        int cb = rest / NC1;
        int m_local = wm * 64 + mi * 16 + (lane >> 2) + ((reg & 1) << 3);
        int k_local = k8b * 8 + (lane & 3) + ((reg >> 1) << 2);
        int co = cb * 128 + m_local;
        int gk = c * 32 + k_local;
        int kw = gk >> 8, ci = gk & 255;
        g_w15P[id] = tf32r(w15[(co * CCH + ci) * 5 + kw]);
    }
}

// ---------------- tf32 mma.sync GEMM ----------------
// stage: A packed 16384B + B row-major 32 x 104 floats (13312B); 3 stages dynamic smem
#define A_BYTES 16384
#define BSTRIDE 104                 // 104 % 32 == 8 -> conflict-free B reads
#define B_BYTES (32 * BSTRIDE * 4)  // 13312
#define STAGE_BYTES (A_BYTES + B_BYTES)   // 29696
#define NSTG 3
#define SMEM_DYN (NSTG * STAGE_BYTES)     // 89088

__global__ __launch_bounds__(256, 2) void gemm_mma(
    int mode,
    const float* __restrict__ bias1,
    const float* __restrict__ bias2)
{
    extern __shared__ __align__(16) char smem[];
    const uint32_t sbase = smem_u32(smem);

    const int tid  = threadIdx.x;
    const int lane = tid & 31;
    const int warp = tid >> 5;
    const int wm = warp >> 2;          // 0..1
    const int wn = warp & 3;           // 0..3
    const int m0 = wm * 64;
    const int n0 = wn * 24;
    const int g  = lane >> 2;          // 0..7
    const int tq = lane & 3;           // 0..3

    const int p0 = blockIdx.x * 96;
    const int b  = p0 / HW;
    const int rr = p0 % HW;
    const int h  = rr / WW;
    const int w0 = rr % WW;            // 0 or 96
    const int cb = blockIdx.y;
    const int co0 = cb * 128;

    const int NC = (mode == 1) ? NC1 : NC2;
    const float* __restrict__ wsrc =
        (mode == 1) ? (g_w15P + (size_t)cb * NC1 * CHUNK_A)
                    : (g_w51P + (size_t)cb * NC2 * CHUNK_A);

    float acc[4][3][4];
    #pragma unroll
    for (int mi = 0; mi < 4; mi++)
        #pragma unroll
        for (int ni = 0; ni < 3; ni++)
            #pragma unroll
            for (int q = 0; q < 4; q++) acc[mi][ni][q] = 0.f;

    auto issue_load = [&](int c) {
        const uint32_t sA = sbase + (c % NSTG) * STAGE_BYTES;
        const uint32_t sB = sA + A_BYTES;
        const float* asrc = wsrc + (size_t)c * CHUNK_A;
        #pragma unroll
        for (int r = 0; r < 4; r++) {
            int s = tid + r * 256;          // 1024 x 16B
            CP_ASYNC16(sA + (uint32_t)s * 16, asrc + s * 4);
        }
        const float* base;
        int rsg;
        bool full25;
        if (mode == 1) {
            int kw = c >> 3, ci0 = (c & 7) << 5;
            base = g_xP + ((size_t)(b * CCH + ci0) * HH + h) * WP + w0 + (kw & ~3);
            rsg = HH * WP; full25 = true;
        } else if (c < NC1) {
            int kh = c >> 3, ci0 = (c & 7) << 5;
            base = g_tmpP + ((size_t)(b * CCH + ci0) * HP + (h + kh)) * WW + w0;
            rsg = HP * WW; full25 = false;
        } else {
            int ci0 = (c - NC1) << 5;
            base = g_xC + ((size_t)(b * CCH + ci0) * HH + h) * WW + w0;
            rsg = HH * WW; full25 = false;
        }
        #pragma unroll
        for (int r = 0; r < 4; r++) {
            int s = tid + r * 256;          // 32 rows x 25 slots = 800
            if (s < 800) {
                int row = s / 25, slot = s - row * 25;
                if (full25 || slot < 24)
                    CP_ASYNC16(sB + (uint32_t)(row * BSTRIDE + slot * 4) * 4,
                               base + (size_t)row * rsg + slot * 4);
            }
        }
        CP_COMMIT();
    };

    issue_load(0);
    issue_load(1);

    for (int c = 0; c < NC; c++) {
        if (c + 1 < NC) { CP_WAIT_1(); } else { CP_WAIT_0(); }
        __syncthreads();

        const char* As = smem + (c % NSTG) * STAGE_BYTES;
        const float* Bs = (const float*)(As + A_BYTES);
        const int off0 = (mode == 1) ? ((c >> 3) & 3) : 0;

        #pragma unroll
        for (int k8b = 0; k8b < 4; k8b++) {
            uint32_t afr[4][4];
            #pragma unroll
            for (int mi = 0; mi < 4; mi++) {
                const uint4 va = *reinterpret_cast<const uint4*>(
                    As + ((((k8b * 2 + wm) * 4 + mi) * 32 + lane) << 4));
                afr[mi][0] = va.x; afr[mi][1] = va.y;
                afr[mi][2] = va.z; afr[mi][3] = va.w;
            }
            #pragma unroll
            for (int ni = 0; ni < 3; ni++) {
                const int nc = off0 + n0 + ni * 8 + g;
                uint32_t bfr[2];
                bfr[0] = __float_as_uint(Bs[(k8b * 8 + tq) * BSTRIDE + nc]);
                bfr[1] = __float_as_uint(Bs[(k8b * 8 + tq + 4) * BSTRIDE + nc]);
                #pragma unroll
                for (int mi = 0; mi < 4; mi++)
                    mma_tf32(acc[mi][ni], afr[mi], bfr);
            }
        }
        if (c + 2 < NC) issue_load(c + 2);   // stage (c+2)%3 last read in chunk c-1 -> safe
    }
    __syncthreads();

    // ---- epilogue ----
    if (mode == 1) {
        #pragma unroll
        for (int mi = 0; mi < 4; mi++) {
            const int coA = co0 + m0 + mi * 16 + g;
            const float bA = bias1[coA];
            const float bB = bias1[coA + 8];
            #pragma unroll
            for (int ni = 0; ni < 3; ni++) {
                const int w = w0 + n0 + ni * 8 + tq * 2;
                float2 vA = make_float2(tf32r(acc[mi][ni][0] + bA),
                                        tf32r(acc[mi][ni][1] + bA));
                float2 vB = make_float2(tf32r(acc[mi][ni][2] + bB),
                                        tf32r(acc[mi][ni][3] + bB));
                size_t rA = ((size_t)(b * CCH + coA) * HP + h + 2) * WW + w;
                size_t rB = ((size_t)(b * CCH + coA + 8) * HP + h + 2) * WW + w;
                *reinterpret_cast<float2*>(g_tmpP + rA) = vA;
                *reinterpret_cast<float2*>(g_tmpP + rB) = vB;
            }
        }
    } else {
        float* s = (float*)smem;                 // [24 pix][132]
        for (int j = 0; j < 4; j++) {
            __syncthreads();
            if (wn == j) {
                #pragma unroll
                for (int mi = 0; mi < 4; mi++) {
                    const int clA = m0 + mi * 16 + g;
                    const float bA = bias1[co0 + clA] + bias2[co0 + clA];
                    const float bB = bias1[co0 + clA + 8] + bias2[co0 + clA + 8];
                    #pragma unroll
                    for (int ni = 0; ni < 3; ni++) {
                        const int nc = ni * 8 + tq * 2;
                        s[nc * 132 + clA]           = acc[mi][ni][0] + bA;
                        s[(nc + 1) * 132 + clA]     = acc[mi][ni][1] + bA;
                        s[nc * 132 + clA + 8]       = acc[mi][ni][2] + bB;
                        s[(nc + 1) * 132 + clA + 8] = acc[mi][ni][3] + bB;
                    }
                }
            }
            __syncthreads();
            #pragma unroll
            for (int r = 0; r < 3; r++) {
                int slot = r * 256 + tid;          // 768 = 24 x 32
                int p = slot >> 5, gg = slot & 31;
                float4 v = *reinterpret_cast<float4*>(&s[p * 132 + gg * 4]);
                size_t dst = ((size_t)(b * HH + h) * WW + w0 + j * 24 + p) * CCH
                           + co0 + gg * 4;
                *reinterpret_cast<float4*>(g_feat + dst) = v;
            }
        }
    }
}

// ---------------- align + residual ----------------
__global__ __launch_bounds__(256) void align_kernel(
    const float* __restrict__ x,
    const float* __restrict__ boxes,
    float* __restrict__ out)
{
    __shared__ float s[32][CCH + 1];
    const int nb = blockIdx.x;
    const int b  = nb / (HH * 6);
    const int r  = nb % (HH * 6);
    const int h  = r / 6;
    const int w0 = (r % 6) * 32;
    const int c  = threadIdx.x;
    const float* __restrict__ featb = g_feat + (size_t)b * HW * CCH;
    const float scale = 0.125f;

    #pragma unroll 1
    for (int p = 0; p < 32; p++) {
        const int pix = h * WW + (w0 + p);
        const float* __restrict__ bx = boxes + ((size_t)b * HW + pix) * 5;
        float yv = bx[0] * scale;
        float xv = bx[1] * scale;
        const bool valid = (yv >= -1.f) & (yv <= (float)HH) &
                           (xv >= -1.f) & (xv <= (float)WW);
        const float fc = featb[(size_t)pix * CCH + c];
        float v = 0.f;
        if (valid) {
            yv = fmaxf(yv, 0.f);
            xv = fmaxf(xv, 0.f);
            int yl = (int)floorf(yv);
            int xl = (int)floorf(xv);
            int yh, xh;
            if (yl >= HH - 1) { yl = HH - 1; yh = HH - 1; yv = (float)(HH - 1); }
            else              { yh = yl + 1; }
            if (xl >= WW - 1) { xl = WW - 1; xh = WW - 1; xv = (float)(WW - 1); }
            else              { xh = xl + 1; }
            const float ly = yv - (float)yl;
            const float lx = xv - (float)xl;
            const float hy = 1.f - ly;
            const float hx = 1.f - lx;
            const float f00 = featb[((size_t)yl * WW + xl) * CCH + c];
            const float f01 = featb[((size_t)yl * WW + xh) * CCH + c];
            const float f10 = featb[((size_t)yh * WW + xl) * CCH + c];
            const float f11 = featb[((size_t)yh * WW + xh) * CCH + c];
            v = hy * hx * f00 + hy * lx * f01 + ly * hx * f10 + ly * lx * f11;
        }
        s[p][c] = fc + v;
    }
    __syncthreads();
    const int wid = c / 32, lane = c % 32;
    const int w = w0 + lane;
    #pragma unroll 1
    for (int i = 0; i < 32; i++) {
        const int cc = wid * 32 + i;
        const size_t gi = ((size_t)(b * CCH + cc) * HH + h) * WW + w;
        out[gi] = x[gi] + s[lane][cc];
    }
}

// ---------------- launch ----------------
extern "C" void kernel_launch(void* const* d_in, const int* in_sizes, int n_in,
                              void* d_out, int out_size)
{
    const float* x     = (const float*)d_in[0];
    const float* boxes = (const float*)d_in[1];
    const float* w51   = (const float*)d_in[2];
    const float* b51   = (const float*)d_in[3];
    const float* w15   = (const float*)d_in[4];
    const float* b15   = (const float*)d_in[5];
    const float* w11   = (const float*)d_in[6];
    const float* b11   = (const float*)d_in[7];
    float* out = (float*)d_out;

    cudaFuncSetAttribute(gemm_mma, cudaFuncAttributeMaxDynamicSharedMemorySize, SMEM_DYN);

    pad_x_kernel   <<<8192, 256>>>(x);
    xc_kernel      <<<2048, 256>>>(x);
    zero_tmp_kernel<<<512, 256>>>();
    wpack_kernel   <<<768, 256>>>(w15, w51, w11);

    dim3 gg(NTOT / 96, 2);   // 768 x 2
    gemm_mma<<<gg, 256, SMEM_DYN>>>(1, b15, b15);
    gemm_mma<<<gg, 256, SMEM_DYN>>>(2, b51, b11);

    align_kernel<<<BATCH * HH * 6, 256>>>(x, boxes, out);
}